// round 5
// baseline (speedup 1.0000x reference)
#include <cuda_runtime.h>
#include <cuda_bf16.h>

// Problem constants (fixed by the reference)
#define N_NODES 8192
#define NFEAT   1024
#define NHID    512
#define OUTD    256
#define BN_EPS  1e-5f

// Scratch for intermediates (allocation-free rule: device globals)
__device__ float g_S1[N_NODES * NHID];   // x @ W1            16 MB
__device__ float g_H [N_NODES * NHID];   // relu(IFadj@S1+b1) 16 MB
__device__ float g_S2[N_NODES * OUTD];   // H @ W2             8 MB

// ---------------------------------------------------------------------------
// Register-blocked fp32 SGEMM.  C[M,N] = A[M,K] @ B[K,N], row-major.
// BM x BN block tile, BK k-tile, TM x TN per-thread tile,
// blockDim.x == (BM/TM)*(BN/TN) == 256.
// Requires: M % BM == 0, N % BN == 0, K % BK == 0, BK % 4 == 0 (float4 loads).
//
// EPI = 0: C = acc
// EPI = 1: C = relu(acc + bias[col])
// EPI = 2: C = (acc + bias[col]) * inv[col] + add[col]   (BatchNorm eval)
//          inv = gamma * rsqrt(var + eps), add = beta - mean*inv
// ---------------------------------------------------------------------------
template<int BM, int BN, int BK, int TM, int TN, int EPI>
__global__ __launch_bounds__(256)
void sgemm_kernel(const float* __restrict__ A,
                  const float* __restrict__ B,
                  float* __restrict__ C,
                  int M, int N, int K,
                  const float* __restrict__ bias,
                  const float* __restrict__ bn_g,
                  const float* __restrict__ bn_b,
                  const float* __restrict__ bn_m,
                  const float* __restrict__ bn_v)
{
    __shared__ float As[BK][BM];   // A tile stored transposed: As[k][m]
    __shared__ float Bs[BK][BN];

    constexpr int NTHREADS = (BM / TM) * (BN / TN);

    const int tid = threadIdx.x;
    const int tx  = tid % (BN / TN);   // thread col index
    const int ty  = tid / (BN / TN);   // thread row index
    const int rowBase = blockIdx.y * BM;
    const int colBase = blockIdx.x * BN;

    float acc[TM][TN];
#pragma unroll
    for (int i = 0; i < TM; i++)
#pragma unroll
        for (int j = 0; j < TN; j++) acc[i][j] = 0.f;

    for (int k0 = 0; k0 < K; k0 += BK) {
        // --- load A tile (BM x BK) with float4, store transposed ---
#pragma unroll
        for (int idx = tid * 4; idx < BM * BK; idx += NTHREADS * 4) {
            const int r = idx / BK;       // row within tile
            const int c = idx % BK;       // col within tile (multiple of 4)
            const float4 v = *reinterpret_cast<const float4*>(
                &A[(long)(rowBase + r) * K + k0 + c]);
            As[c + 0][r] = v.x;
            As[c + 1][r] = v.y;
            As[c + 2][r] = v.z;
            As[c + 3][r] = v.w;
        }
        // --- load B tile (BK x BN) with float4 ---
#pragma unroll
        for (int idx = tid * 4; idx < BK * BN; idx += NTHREADS * 4) {
            const int r = idx / BN;
            const int c = idx % BN;       // multiple of 4 (BN % 4 == 0)
            const float4 v = *reinterpret_cast<const float4*>(
                &B[(long)(k0 + r) * N + colBase + c]);
            *reinterpret_cast<float4*>(&Bs[r][c]) = v;
        }
        __syncthreads();

        // --- compute: BK outer products of 8/4-wide register fragments ---
#pragma unroll
        for (int kk = 0; kk < BK; kk++) {
            float a[TM], b[TN];
#pragma unroll
            for (int i = 0; i < TM; i++) a[i] = As[kk][ty * TM + i];
#pragma unroll
            for (int j = 0; j < TN; j++) b[j] = Bs[kk][tx * TN + j];
#pragma unroll
            for (int i = 0; i < TM; i++)
#pragma unroll
                for (int j = 0; j < TN; j++)
                    acc[i][j] = fmaf(a[i], b[j], acc[i][j]);
        }
        __syncthreads();
    }

    // --- epilogue (per-column params computed once) ---
    float bi[TN], inv[TN], add[TN];
#pragma unroll
    for (int j = 0; j < TN; j++) {
        const int col = colBase + tx * TN + j;
        bi[j]  = (EPI >= 1) ? bias[col] : 0.f;
        inv[j] = 1.f;
        add[j] = 0.f;
        if (EPI == 2) {
            const float iv = bn_g[col] * rsqrtf(bn_v[col] + BN_EPS);
            inv[j] = iv;
            add[j] = bn_b[col] - bn_m[col] * iv;
        }
    }

#pragma unroll
    for (int i = 0; i < TM; i++) {
        const int row = rowBase + ty * TM + i;
        float o[TN];
#pragma unroll
        for (int j = 0; j < TN; j++) {
            float v = acc[i][j] + bi[j];
            if (EPI == 1) v = fmaxf(v, 0.f);
            if (EPI == 2) v = v * inv[j] + add[j];
            o[j] = v;
        }
#pragma unroll
        for (int j = 0; j < TN; j += 4) {
            *reinterpret_cast<float4*>(
                &C[(long)row * N + colBase + tx * TN + j]) =
                make_float4(o[j], o[j + 1], o[j + 2], o[j + 3]);
        }
    }
}

extern "C" void kernel_launch(void* const* d_in, const int* in_sizes, int n_in,
                              void* d_out, int out_size)
{
    // metadata order == setup_inputs dict order
    const float* x     = (const float*)d_in[0];   // [8192, 1024]
    const float* IFadj = (const float*)d_in[1];   // [8192, 8192]
    const float* adj   = (const float*)d_in[2];   // [8192, 8192]
    const float* W1    = (const float*)d_in[3];   // [1024, 512]
    const float* b1    = (const float*)d_in[4];   // [512]
    const float* W2    = (const float*)d_in[5];   // [512, 256]
    const float* b2    = (const float*)d_in[6];   // [256]
    const float* bng   = (const float*)d_in[7];
    const float* bnb   = (const float*)d_in[8];
    const float* bnm   = (const float*)d_in[9];
    const float* bnv   = (const float*)d_in[10];
    float* out = (float*)d_out;                   // [8192, 256] fp32

    float *s1, *h, *s2;
    cudaGetSymbolAddress((void**)&s1, g_S1);
    cudaGetSymbolAddress((void**)&h,  g_H);
    cudaGetSymbolAddress((void**)&s2, g_S2);

    const dim3 blk(256);

    // 1) S1 = x @ W1                       M=8192 N=512 K=1024
    sgemm_kernel<128, 128, 8, 8, 8, 0>
        <<<dim3(NHID / 128, N_NODES / 128), blk>>>(
            x, W1, s1, N_NODES, NHID, NFEAT,
            nullptr, nullptr, nullptr, nullptr, nullptr);

    // 2) H = relu(IFadj @ S1 + b1)         M=8192 N=512 K=8192  (dominant)
    sgemm_kernel<128, 128, 8, 8, 8, 1>
        <<<dim3(NHID / 128, N_NODES / 128), blk>>>(
            IFadj, s1, h, N_NODES, NHID, N_NODES,
            b1, nullptr, nullptr, nullptr, nullptr);

    // 3) S2 = H @ W2                       M=8192 N=256 K=512
    //    64-row tiles -> 256 CTAs so the whole chip stays busy at N=256.
    sgemm_kernel<64, 128, 8, 4, 8, 0>
        <<<dim3(OUTD / 128, N_NODES / 64), blk>>>(
            h, W2, s2, N_NODES, OUTD, NHID,
            nullptr, nullptr, nullptr, nullptr, nullptr);

    // 4) out = BN(adj @ S2 + b2)           M=8192 N=256 K=8192
    sgemm_kernel<64, 128, 8, 4, 8, 2>
        <<<dim3(OUTD / 128, N_NODES / 64), blk>>>(
            adj, s2, out, N_NODES, OUTD, N_NODES,
            b2, bng, bnb, bnm, bnv);
}

// round 8
// speedup vs baseline: 3.4333x; 3.4333x over previous
#include <cuda_runtime.h>
#include <cuda_bf16.h>
#include <cstdint>

// Problem constants
#define N_NODES 8192
#define NFEAT   1024
#define NHID    512
#define OUTD    256
#define BN_EPS  1e-5f

// Intermediates (allocation-free rule: device globals)
__device__ float g_S1[N_NODES * NHID];   // x @ W1
__device__ float g_H [N_NODES * NHID];   // relu(IFadj@S1 + b1)
__device__ float g_S2[N_NODES * OUTD];   // H @ W2

// ---------------------------------------------------------------------------
// helpers
// ---------------------------------------------------------------------------
__device__ __forceinline__ uint32_t smem_u32(const void* p) {
    uint32_t a;
    asm("{ .reg .u64 t; cvta.to.shared.u64 t, %1; cvt.u32.u64 %0, t; }"
        : "=r"(a) : "l"(p));
    return a;
}

// Swizzles (conflict-free ldmatrix):
// A tile: 128 rows x 64B (32 bf16 k).  chunk bits [4:5] ^= row bits [7:8]
__device__ __forceinline__ uint32_t sw_a(uint32_t o) { return o ^ ((o >> 3) & 0x30); }
// B tile: 32 rows x 256B (128 bf16 n). chunk bits [4:6] ^= row bits [8:10]
__device__ __forceinline__ uint32_t sw_b(uint32_t o) { return o ^ ((o >> 4) & 0x70); }

__device__ __forceinline__ void ldsm_x4(uint32_t r[4], uint32_t addr) {
    asm volatile("ldmatrix.sync.aligned.m8n8.x4.shared.b16 {%0,%1,%2,%3}, [%4];"
        : "=r"(r[0]), "=r"(r[1]), "=r"(r[2]), "=r"(r[3]) : "r"(addr));
}
__device__ __forceinline__ void ldsm_x4_t(uint32_t r[4], uint32_t addr) {
    asm volatile("ldmatrix.sync.aligned.m8n8.x4.trans.shared.b16 {%0,%1,%2,%3}, [%4];"
        : "=r"(r[0]), "=r"(r[1]), "=r"(r[2]), "=r"(r[3]) : "r"(addr));
}

__device__ __forceinline__ void mma_bf16(float* c, const uint32_t a[4],
                                         uint32_t b0, uint32_t b1) {
    asm volatile(
        "mma.sync.aligned.m16n8k16.row.col.f32.bf16.bf16.f32 "
        "{%0,%1,%2,%3}, {%4,%5,%6,%7}, {%8,%9}, {%0,%1,%2,%3};"
        : "+f"(c[0]), "+f"(c[1]), "+f"(c[2]), "+f"(c[3])
        : "r"(a[0]), "r"(a[1]), "r"(a[2]), "r"(a[3]), "r"(b0), "r"(b1));
}

// fp32 pair -> (hi, lo) bf16x2
__device__ __forceinline__ void split_pack(float a, float b, uint32_t& hi, uint32_t& lo) {
    __nv_bfloat162 h = __floats2bfloat162_rn(a, b);
    float ra = a - __bfloat162float(h.x);
    float rb = b - __bfloat162float(h.y);
    __nv_bfloat162 l = __floats2bfloat162_rn(ra, rb);
    hi = *reinterpret_cast<uint32_t*>(&h);
    lo = *reinterpret_cast<uint32_t*>(&l);
}

// ---------------------------------------------------------------------------
// Split-precision bf16 mma.sync GEMM.  C[M,N] = A[M,K] @ B[K,N] (fp32 in/out).
// CTA tile 128x128, BK=32, 256 threads = 8 warps (2M x 4N), warp tile 64x32.
// 3 MMA products per fragment pair: Ah*Bh + Ah*Bl + Al*Bh  (lo*lo dropped).
// EPI 0: none | 1: relu(+bias) | 2: BatchNorm eval (+bias)
// ---------------------------------------------------------------------------
template<int EPI>
__global__ __launch_bounds__(256, 1)
void mma_gemm(const float* __restrict__ A, const float* __restrict__ B,
              float* __restrict__ C, int M, int N, int K,
              const float* __restrict__ bias,
              const float* __restrict__ bng, const float* __restrict__ bnb,
              const float* __restrict__ bnm, const float* __restrict__ bnv)
{
    // SMEM: Ahi 8K | Alo 8K | Bhi 8K | Blo 8K = 32 KB (single buffer, reg prefetch)
    __shared__ __align__(128) char smc[32768];
    const uint32_t sbase = smem_u32(smc);
    const uint32_t sA_hi = sbase;
    const uint32_t sA_lo = sbase + 8192;
    const uint32_t sB_hi = sbase + 16384;
    const uint32_t sB_lo = sbase + 24576;

    const int tid  = threadIdx.x;
    const int lane = tid & 31;
    const int wid  = tid >> 5;
    const int wm   = (wid >> 2) * 64;    // warp M offset within CTA tile
    const int wn   = (wid & 3) * 32;     // warp N offset
    const int rowBase = blockIdx.y * 128;
    const int colBase = blockIdx.x * 128;

    float acc[4][4][4];
#pragma unroll
    for (int i = 0; i < 4; i++)
#pragma unroll
        for (int j = 0; j < 4; j++)
#pragma unroll
            for (int r = 0; r < 4; r++) acc[i][j][r] = 0.f;

    // GMEM staging registers
    float4 stA[4];        // A: 4 slots, (tid + s*256)*4 -> m = idx>>5, k = idx&31
    float4 stB[2][2];     // B: 2 slots, (tid + s*256)*8 -> k = idx>>7, n = idx&127

    auto ldg = [&](int k0) {
#pragma unroll
        for (int s = 0; s < 4; s++) {
            const int idx = (tid + s * 256) * 4;
            const int m = idx >> 5, k = idx & 31;
            stA[s] = *reinterpret_cast<const float4*>(
                A + (size_t)(rowBase + m) * K + k0 + k);
        }
#pragma unroll
        for (int s = 0; s < 2; s++) {
            const int idx = (tid + s * 256) * 8;
            const int k = idx >> 7, n = idx & 127;
            const float* p = B + (size_t)(k0 + k) * N + colBase + n;
            stB[s][0] = *reinterpret_cast<const float4*>(p);
            stB[s][1] = *reinterpret_cast<const float4*>(p + 4);
        }
    };

    auto sts = [&]() {
#pragma unroll
        for (int s = 0; s < 4; s++) {
            const int idx = (tid + s * 256) * 4;
            const int m = idx >> 5, k = idx & 31;
            uint32_t h0, l0, h1, l1;
            split_pack(stA[s].x, stA[s].y, h0, l0);
            split_pack(stA[s].z, stA[s].w, h1, l1);
            const uint32_t off = sw_a((uint32_t)(m * 64 + k * 2));  // 8B aligned
            *reinterpret_cast<uint2*>(smc + off)        = make_uint2(h0, h1);
            *reinterpret_cast<uint2*>(smc + 8192 + off) = make_uint2(l0, l1);
        }
#pragma unroll
        for (int s = 0; s < 2; s++) {
            const int idx = (tid + s * 256) * 8;
            const int k = idx >> 7, n = idx & 127;
            uint32_t h[4], l[4];
            split_pack(stB[s][0].x, stB[s][0].y, h[0], l[0]);
            split_pack(stB[s][0].z, stB[s][0].w, h[1], l[1]);
            split_pack(stB[s][1].x, stB[s][1].y, h[2], l[2]);
            split_pack(stB[s][1].z, stB[s][1].w, h[3], l[3]);
            const uint32_t off = sw_b((uint32_t)(k * 256 + n * 2));  // 16B aligned
            *reinterpret_cast<uint4*>(smc + 16384 + off) = make_uint4(h[0], h[1], h[2], h[3]);
            *reinterpret_cast<uint4*>(smc + 24576 + off) = make_uint4(l[0], l[1], l[2], l[3]);
        }
    };

    auto compute = [&]() {
#pragma unroll
        for (int ks = 0; ks < 2; ks++) {
            const int k0 = ks * 16;
            // A fragments: hi/lo, 4 m-frags of 16x16
            uint32_t af[2][4][4];
            {
                const int m_lane = lane & 15;
                const int k_lane = k0 + ((lane >> 4) << 3);
#pragma unroll
                for (int mf = 0; mf < 4; mf++) {
                    const uint32_t off = sw_a(
                        (uint32_t)((wm + mf * 16 + m_lane) * 64 + k_lane * 2));
                    ldsm_x4(af[0][mf], sA_hi + off);
                    ldsm_x4(af[1][mf], sA_lo + off);
                }
            }
            // B fragments: hi/lo, 2 groups x4.trans, each covers 2 n-frags
            uint32_t bfr[2][2][4];
            {
                const int mat = lane >> 3, wi = lane & 7;
                const int k_lane = k0 + (mat & 1) * 8 + wi;
#pragma unroll
                for (int grp = 0; grp < 2; grp++) {
                    const int n_lane = wn + grp * 16 + (mat >> 1) * 8;
                    const uint32_t off = sw_b((uint32_t)(k_lane * 256 + n_lane * 2));
                    ldsm_x4_t(bfr[0][grp], sB_hi + off);
                    ldsm_x4_t(bfr[1][grp], sB_lo + off);
                }
            }
#pragma unroll
            for (int mf = 0; mf < 4; mf++)
#pragma unroll
                for (int nf = 0; nf < 4; nf++) {
                    const int g = nf >> 1, q = (nf & 1) * 2;
                    mma_bf16(acc[mf][nf], af[0][mf], bfr[0][g][q], bfr[0][g][q + 1]); // Ah*Bh
                    mma_bf16(acc[mf][nf], af[0][mf], bfr[1][g][q], bfr[1][g][q + 1]); // Ah*Bl
                    mma_bf16(acc[mf][nf], af[1][mf], bfr[0][g][q], bfr[0][g][q + 1]); // Al*Bh
                }
        }
    };

    const int nk = K >> 5;   // K / 32
    ldg(0);
    sts();
    __syncthreads();
    for (int it = 0; it < nk; it++) {
        if (it + 1 < nk) ldg((it + 1) << 5);   // prefetch next chunk to regs
        compute();
        __syncthreads();                        // WAR: everyone done reading smem
        if (it + 1 < nk) { sts(); __syncthreads(); }
    }

    // ---- epilogue ----
    const int g   = lane >> 2;
    const int tig = lane & 3;
#pragma unroll
    for (int mf = 0; mf < 4; mf++) {
#pragma unroll
        for (int nf = 0; nf < 4; nf++) {
            const int row = rowBase + wm + mf * 16 + g;
            const int col = colBase + wn + nf * 8 + tig * 2;
            float v0 = acc[mf][nf][0], v1 = acc[mf][nf][1];
            float v2 = acc[mf][nf][2], v3 = acc[mf][nf][3];
            if constexpr (EPI >= 1) {
                const float b0 = bias[col], b1 = bias[col + 1];
                v0 += b0; v1 += b1; v2 += b0; v3 += b1;
            }
            if constexpr (EPI == 1) {
                v0 = fmaxf(v0, 0.f); v1 = fmaxf(v1, 0.f);
                v2 = fmaxf(v2, 0.f); v3 = fmaxf(v3, 0.f);
            }
            if constexpr (EPI == 2) {
                const float i0 = bng[col]     * rsqrtf(bnv[col]     + BN_EPS);
                const float i1 = bng[col + 1] * rsqrtf(bnv[col + 1] + BN_EPS);
                const float a0 = bnb[col]     - bnm[col]     * i0;
                const float a1 = bnb[col + 1] - bnm[col + 1] * i1;
                v0 = v0 * i0 + a0; v1 = v1 * i1 + a1;
                v2 = v2 * i0 + a0; v3 = v3 * i1 + a1;
            }
            *reinterpret_cast<float2*>(C + (size_t)row * N + col)       = make_float2(v0, v1);
            *reinterpret_cast<float2*>(C + (size_t)(row + 8) * N + col) = make_float2(v2, v3);
        }
    }
}

// ---------------------------------------------------------------------------
extern "C" void kernel_launch(void* const* d_in, const int* in_sizes, int n_in,
                              void* d_out, int out_size)
{
    const float* x     = (const float*)d_in[0];
    const float* IFadj = (const float*)d_in[1];
    const float* adj   = (const float*)d_in[2];
    const float* W1    = (const float*)d_in[3];
    const float* b1    = (const float*)d_in[4];
    const float* W2    = (const float*)d_in[5];
    const float* b2    = (const float*)d_in[6];
    const float* bng   = (const float*)d_in[7];
    const float* bnb   = (const float*)d_in[8];
    const float* bnm   = (const float*)d_in[9];
    const float* bnv   = (const float*)d_in[10];
    float* out = (float*)d_out;

    float *s1, *h, *s2;
    cudaGetSymbolAddress((void**)&s1, g_S1);
    cudaGetSymbolAddress((void**)&h,  g_H);
    cudaGetSymbolAddress((void**)&s2, g_S2);

    const dim3 blk(256);

    // 1) S1 = x @ W1                      M=8192 N=512 K=1024
    mma_gemm<0><<<dim3(NHID / 128, N_NODES / 128), blk>>>(
        x, W1, s1, N_NODES, NHID, NFEAT, nullptr, nullptr, nullptr, nullptr, nullptr);

    // 2) H = relu(IFadj @ S1 + b1)        M=8192 N=512 K=8192  (dominant)
    mma_gemm<1><<<dim3(NHID / 128, N_NODES / 128), blk>>>(
        IFadj, s1, h, N_NODES, NHID, N_NODES, b1, nullptr, nullptr, nullptr, nullptr);

    // 3) S2 = H @ W2                      M=8192 N=256 K=512
    mma_gemm<0><<<dim3(OUTD / 128, N_NODES / 128), blk>>>(
        h, W2, s2, N_NODES, OUTD, NHID, nullptr, nullptr, nullptr, nullptr, nullptr);

    // 4) out = BN(adj @ S2 + b2)          M=8192 N=256 K=8192
    mma_gemm<2><<<dim3(OUTD / 128, N_NODES / 128), blk>>>(
        adj, s2, out, N_NODES, OUTD, N_NODES, b2, bng, bnb, bnm, bnv);
}

// round 9
// speedup vs baseline: 3.4414x; 1.0024x over previous
#include <cuda_runtime.h>
#include <cuda_bf16.h>
#include <cstdint>

// Problem constants
#define N_NODES 8192
#define NFEAT   1024
#define NHID    512
#define OUTD    256
#define BN_EPS  1e-5f

// Intermediates (allocation-free rule: device globals)
__device__ float g_S1[N_NODES * NHID];   // x @ W1
__device__ float g_H [N_NODES * NHID];   // relu(IFadj@S1 + b1)
__device__ float g_S2[N_NODES * OUTD];   // H @ W2

// ---------------------------------------------------------------------------
// helpers
// ---------------------------------------------------------------------------
__device__ __forceinline__ uint32_t smem_u32(const void* p) {
    uint32_t a;
    asm("{ .reg .u64 t; cvta.to.shared.u64 t, %1; cvt.u32.u64 %0, t; }"
        : "=r"(a) : "l"(p));
    return a;
}

// Swizzles (conflict-free ldmatrix):
// A tile: 128 rows x 64B (32 bf16 k).  chunk bits [4:5] ^= row bits [7:8]
__device__ __forceinline__ uint32_t sw_a(uint32_t o) { return o ^ ((o >> 3) & 0x30); }
// B tile: 32 rows x 256B (128 bf16 n). chunk bits [4:6] ^= row bits [8:10]
__device__ __forceinline__ uint32_t sw_b(uint32_t o) { return o ^ ((o >> 4) & 0x70); }

__device__ __forceinline__ void ldsm_x4(uint32_t r[4], uint32_t addr) {
    asm volatile("ldmatrix.sync.aligned.m8n8.x4.shared.b16 {%0,%1,%2,%3}, [%4];"
        : "=r"(r[0]), "=r"(r[1]), "=r"(r[2]), "=r"(r[3]) : "r"(addr));
}
__device__ __forceinline__ void ldsm_x4_t(uint32_t r[4], uint32_t addr) {
    asm volatile("ldmatrix.sync.aligned.m8n8.x4.trans.shared.b16 {%0,%1,%2,%3}, [%4];"
        : "=r"(r[0]), "=r"(r[1]), "=r"(r[2]), "=r"(r[3]) : "r"(addr));
}

__device__ __forceinline__ void mma_bf16(float* c, const uint32_t a[4],
                                         uint32_t b0, uint32_t b1) {
    asm volatile(
        "mma.sync.aligned.m16n8k16.row.col.f32.bf16.bf16.f32 "
        "{%0,%1,%2,%3}, {%4,%5,%6,%7}, {%8,%9}, {%0,%1,%2,%3};"
        : "+f"(c[0]), "+f"(c[1]), "+f"(c[2]), "+f"(c[3])
        : "r"(a[0]), "r"(a[1]), "r"(a[2]), "r"(a[3]), "r"(b0), "r"(b1));
}

// fp32 pair -> (hi, lo) bf16x2
__device__ __forceinline__ void split_pack(float a, float b, uint32_t& hi, uint32_t& lo) {
    __nv_bfloat162 h = __floats2bfloat162_rn(a, b);
    float ra = a - __bfloat162float(h.x);
    float rb = b - __bfloat162float(h.y);
    __nv_bfloat162 l = __floats2bfloat162_rn(ra, rb);
    hi = *reinterpret_cast<uint32_t*>(&h);
    lo = *reinterpret_cast<uint32_t*>(&l);
}

// ---------------------------------------------------------------------------
// Split-precision bf16 mma.sync GEMM.  C[M,N] = A[M,K] @ B[K,N] (fp32 in/out).
// CTA tile 128x128, BK=32, 256 threads = 8 warps (2M x 4N), warp tile 64x32.
// 3 MMA products per fragment pair: Ah*Bh + Ah*Bl + Al*Bh  (lo*lo dropped).
// EPI 0: none | 1: relu(+bias) | 2: BatchNorm eval (+bias)
// ---------------------------------------------------------------------------
template<int EPI>
__global__ __launch_bounds__(256, 1)
void mma_gemm(const float* __restrict__ A, const float* __restrict__ B,
              float* __restrict__ C, int M, int N, int K,
              const float* __restrict__ bias,
              const float* __restrict__ bng, const float* __restrict__ bnb,
              const float* __restrict__ bnm, const float* __restrict__ bnv)
{
    // SMEM: Ahi 8K | Alo 8K | Bhi 8K | Blo 8K = 32 KB (single buffer, reg prefetch)
    __shared__ __align__(128) char smc[32768];
    const uint32_t sbase = smem_u32(smc);
    const uint32_t sA_hi = sbase;
    const uint32_t sA_lo = sbase + 8192;
    const uint32_t sB_hi = sbase + 16384;
    const uint32_t sB_lo = sbase + 24576;

    const int tid  = threadIdx.x;
    const int lane = tid & 31;
    const int wid  = tid >> 5;
    const int wm   = (wid >> 2) * 64;    // warp M offset within CTA tile
    const int wn   = (wid & 3) * 32;     // warp N offset
    const int rowBase = blockIdx.y * 128;
    const int colBase = blockIdx.x * 128;

    float acc[4][4][4];
#pragma unroll
    for (int i = 0; i < 4; i++)
#pragma unroll
        for (int j = 0; j < 4; j++)
#pragma unroll
            for (int r = 0; r < 4; r++) acc[i][j][r] = 0.f;

    // GMEM staging registers
    float4 stA[4];        // A: 4 slots, (tid + s*256)*4 -> m = idx>>5, k = idx&31
    float4 stB[2][2];     // B: 2 slots, (tid + s*256)*8 -> k = idx>>7, n = idx&127

    auto ldg = [&](int k0) {
#pragma unroll
        for (int s = 0; s < 4; s++) {
            const int idx = (tid + s * 256) * 4;
            const int m = idx >> 5, k = idx & 31;
            stA[s] = *reinterpret_cast<const float4*>(
                A + (size_t)(rowBase + m) * K + k0 + k);
        }
#pragma unroll
        for (int s = 0; s < 2; s++) {
            const int idx = (tid + s * 256) * 8;
            const int k = idx >> 7, n = idx & 127;
            const float* p = B + (size_t)(k0 + k) * N + colBase + n;
            stB[s][0] = *reinterpret_cast<const float4*>(p);
            stB[s][1] = *reinterpret_cast<const float4*>(p + 4);
        }
    };

    auto sts = [&]() {
#pragma unroll
        for (int s = 0; s < 4; s++) {
            const int idx = (tid + s * 256) * 4;
            const int m = idx >> 5, k = idx & 31;
            uint32_t h0, l0, h1, l1;
            split_pack(stA[s].x, stA[s].y, h0, l0);
            split_pack(stA[s].z, stA[s].w, h1, l1);
            const uint32_t off = sw_a((uint32_t)(m * 64 + k * 2));  // 8B aligned
            *reinterpret_cast<uint2*>(smc + off)        = make_uint2(h0, h1);
            *reinterpret_cast<uint2*>(smc + 8192 + off) = make_uint2(l0, l1);
        }
#pragma unroll
        for (int s = 0; s < 2; s++) {
            const int idx = (tid + s * 256) * 8;
            const int k = idx >> 7, n = idx & 127;
            uint32_t h[4], l[4];
            split_pack(stB[s][0].x, stB[s][0].y, h[0], l[0]);
            split_pack(stB[s][0].z, stB[s][0].w, h[1], l[1]);
            split_pack(stB[s][1].x, stB[s][1].y, h[2], l[2]);
            split_pack(stB[s][1].z, stB[s][1].w, h[3], l[3]);
            const uint32_t off = sw_b((uint32_t)(k * 256 + n * 2));  // 16B aligned
            *reinterpret_cast<uint4*>(smc + 16384 + off) = make_uint4(h[0], h[1], h[2], h[3]);
            *reinterpret_cast<uint4*>(smc + 24576 + off) = make_uint4(l[0], l[1], l[2], l[3]);
        }
    };

    auto compute = [&]() {
#pragma unroll
        for (int ks = 0; ks < 2; ks++) {
            const int k0 = ks * 16;
            // A fragments: hi/lo, 4 m-frags of 16x16
            uint32_t af[2][4][4];
            {
                const int m_lane = lane & 15;
                const int k_lane = k0 + ((lane >> 4) << 3);
#pragma unroll
                for (int mf = 0; mf < 4; mf++) {
                    const uint32_t off = sw_a(
                        (uint32_t)((wm + mf * 16 + m_lane) * 64 + k_lane * 2));
                    ldsm_x4(af[0][mf], sA_hi + off);
                    ldsm_x4(af[1][mf], sA_lo + off);
                }
            }
            // B fragments: hi/lo, 2 groups x4.trans, each covers 2 n-frags
            uint32_t bfr[2][2][4];
            {
                const int mat = lane >> 3, wi = lane & 7;
                const int k_lane = k0 + (mat & 1) * 8 + wi;
#pragma unroll
                for (int grp = 0; grp < 2; grp++) {
                    const int n_lane = wn + grp * 16 + (mat >> 1) * 8;
                    const uint32_t off = sw_b((uint32_t)(k_lane * 256 + n_lane * 2));
                    ldsm_x4_t(bfr[0][grp], sB_hi + off);
                    ldsm_x4_t(bfr[1][grp], sB_lo + off);
                }
            }
#pragma unroll
            for (int mf = 0; mf < 4; mf++)
#pragma unroll
                for (int nf = 0; nf < 4; nf++) {
                    const int g = nf >> 1, q = (nf & 1) * 2;
                    mma_bf16(acc[mf][nf], af[0][mf], bfr[0][g][q], bfr[0][g][q + 1]); // Ah*Bh
                    mma_bf16(acc[mf][nf], af[0][mf], bfr[1][g][q], bfr[1][g][q + 1]); // Ah*Bl
                    mma_bf16(acc[mf][nf], af[1][mf], bfr[0][g][q], bfr[0][g][q + 1]); // Al*Bh
                }
        }
    };

    const int nk = K >> 5;   // K / 32
    ldg(0);
    sts();
    __syncthreads();
    for (int it = 0; it < nk; it++) {
        if (it + 1 < nk) ldg((it + 1) << 5);   // prefetch next chunk to regs
        compute();
        __syncthreads();                        // WAR: everyone done reading smem
        if (it + 1 < nk) { sts(); __syncthreads(); }
    }

    // ---- epilogue ----
    const int g   = lane >> 2;
    const int tig = lane & 3;
#pragma unroll
    for (int mf = 0; mf < 4; mf++) {
#pragma unroll
        for (int nf = 0; nf < 4; nf++) {
            const int row = rowBase + wm + mf * 16 + g;
            const int col = colBase + wn + nf * 8 + tig * 2;
            float v0 = acc[mf][nf][0], v1 = acc[mf][nf][1];
            float v2 = acc[mf][nf][2], v3 = acc[mf][nf][3];
            if constexpr (EPI >= 1) {
                const float b0 = bias[col], b1 = bias[col + 1];
                v0 += b0; v1 += b1; v2 += b0; v3 += b1;
            }
            if constexpr (EPI == 1) {
                v0 = fmaxf(v0, 0.f); v1 = fmaxf(v1, 0.f);
                v2 = fmaxf(v2, 0.f); v3 = fmaxf(v3, 0.f);
            }
            if constexpr (EPI == 2) {
                const float i0 = bng[col]     * rsqrtf(bnv[col]     + BN_EPS);
                const float i1 = bng[col + 1] * rsqrtf(bnv[col + 1] + BN_EPS);
                const float a0 = bnb[col]     - bnm[col]     * i0;
                const float a1 = bnb[col + 1] - bnm[col + 1] * i1;
                v0 = v0 * i0 + a0; v1 = v1 * i1 + a1;
                v2 = v2 * i0 + a0; v3 = v3 * i1 + a1;
            }
            *reinterpret_cast<float2*>(C + (size_t)row * N + col)       = make_float2(v0, v1);
            *reinterpret_cast<float2*>(C + (size_t)(row + 8) * N + col) = make_float2(v2, v3);
        }
    }
}

// ---------------------------------------------------------------------------
extern "C" void kernel_launch(void* const* d_in, const int* in_sizes, int n_in,
                              void* d_out, int out_size)
{
    const float* x     = (const float*)d_in[0];
    const float* IFadj = (const float*)d_in[1];
    const float* adj   = (const float*)d_in[2];
    const float* W1    = (const float*)d_in[3];
    const float* b1    = (const float*)d_in[4];
    const float* W2    = (const float*)d_in[5];
    const float* b2    = (const float*)d_in[6];
    const float* bng   = (const float*)d_in[7];
    const float* bnb   = (const float*)d_in[8];
    const float* bnm   = (const float*)d_in[9];
    const float* bnv   = (const float*)d_in[10];
    float* out = (float*)d_out;

    float *s1, *h, *s2;
    cudaGetSymbolAddress((void**)&s1, g_S1);
    cudaGetSymbolAddress((void**)&h,  g_H);
    cudaGetSymbolAddress((void**)&s2, g_S2);

    const dim3 blk(256);

    // 1) S1 = x @ W1                      M=8192 N=512 K=1024
    mma_gemm<0><<<dim3(NHID / 128, N_NODES / 128), blk>>>(
        x, W1, s1, N_NODES, NHID, NFEAT, nullptr, nullptr, nullptr, nullptr, nullptr);

    // 2) H = relu(IFadj @ S1 + b1)        M=8192 N=512 K=8192  (dominant)
    mma_gemm<1><<<dim3(NHID / 128, N_NODES / 128), blk>>>(
        IFadj, s1, h, N_NODES, NHID, N_NODES, b1, nullptr, nullptr, nullptr, nullptr);

    // 3) S2 = H @ W2                      M=8192 N=256 K=512
    mma_gemm<0><<<dim3(OUTD / 128, N_NODES / 128), blk>>>(
        h, W2, s2, N_NODES, OUTD, NHID, nullptr, nullptr, nullptr, nullptr, nullptr);

    // 4) out = BN(adj @ S2 + b2)          M=8192 N=256 K=8192
    mma_gemm<2><<<dim3(OUTD / 128, N_NODES / 128), blk>>>(
        adj, s2, out, N_NODES, OUTD, N_NODES, b2, bng, bnb, bnm, bnv);
}

// round 10
// speedup vs baseline: 3.6435x; 1.0587x over previous
#include <cuda_runtime.h>
#include <cuda_bf16.h>
#include <cstdint>

// Problem constants
#define N_NODES 8192
#define NFEAT   1024
#define NHID    512
#define OUTD    256
#define BN_EPS  1e-5f

// Intermediates (allocation-free rule: device globals)
__device__ float g_S1[N_NODES * NHID];   // x @ W1
__device__ float g_H [N_NODES * NHID];   // relu(IFadj@S1 + b1)
__device__ float g_S2[N_NODES * OUTD];   // H @ W2

// ---------------------------------------------------------------------------
// helpers
// ---------------------------------------------------------------------------
__device__ __forceinline__ uint32_t smem_u32(const void* p) {
    uint32_t a;
    asm("{ .reg .u64 t; cvta.to.shared.u64 t, %1; cvt.u32.u64 %0, t; }"
        : "=r"(a) : "l"(p));
    return a;
}

// Swizzles (conflict-free ldmatrix):
// A tile: 128 rows x 64B (32 bf16 k).  chunk bits [4:5] ^= row bits [7:8]
__device__ __forceinline__ uint32_t sw_a(uint32_t o) { return o ^ ((o >> 3) & 0x30); }
// B tile: 32 rows x 256B (128 bf16 n). chunk bits [4:6] ^= row bits [8:10]
__device__ __forceinline__ uint32_t sw_b(uint32_t o) { return o ^ ((o >> 4) & 0x70); }

__device__ __forceinline__ void ldsm_x4(uint32_t r[4], uint32_t addr) {
    asm volatile("ldmatrix.sync.aligned.m8n8.x4.shared.b16 {%0,%1,%2,%3}, [%4];"
        : "=r"(r[0]), "=r"(r[1]), "=r"(r[2]), "=r"(r[3]) : "r"(addr));
}
__device__ __forceinline__ void ldsm_x4_t(uint32_t r[4], uint32_t addr) {
    asm volatile("ldmatrix.sync.aligned.m8n8.x4.trans.shared.b16 {%0,%1,%2,%3}, [%4];"
        : "=r"(r[0]), "=r"(r[1]), "=r"(r[2]), "=r"(r[3]) : "r"(addr));
}

__device__ __forceinline__ void mma_bf16(float* c, const uint32_t a[4],
                                         uint32_t b0, uint32_t b1) {
    asm volatile(
        "mma.sync.aligned.m16n8k16.row.col.f32.bf16.bf16.f32 "
        "{%0,%1,%2,%3}, {%4,%5,%6,%7}, {%8,%9}, {%0,%1,%2,%3};"
        : "+f"(c[0]), "+f"(c[1]), "+f"(c[2]), "+f"(c[3])
        : "r"(a[0]), "r"(a[1]), "r"(a[2]), "r"(a[3]), "r"(b0), "r"(b1));
}

// fp32 pair -> (hi, lo) bf16x2
__device__ __forceinline__ void split_pack(float a, float b, uint32_t& hi, uint32_t& lo) {
    __nv_bfloat162 h = __floats2bfloat162_rn(a, b);
    float ra = a - __bfloat162float(h.x);
    float rb = b - __bfloat162float(h.y);
    __nv_bfloat162 l = __floats2bfloat162_rn(ra, rb);
    hi = *reinterpret_cast<uint32_t*>(&h);
    lo = *reinterpret_cast<uint32_t*>(&l);
}

// ---------------------------------------------------------------------------
// Split-precision bf16 mma.sync GEMM.  C[M,N] = A[M,K] @ B[K,N] (fp32 in/out).
// CTA tile 128x128, BK=32, 256 threads = 8 warps (2M x 4N), warp tile 64x32.
// DOUBLE-BUFFERED SMEM (2 x 32KB), one __syncthreads per K-chunk:
//   ldg(it+1) -> compute(buf) -> sts(buf^1) -> sync
// 3 MMA products per fragment pair: Ah*Bh + Ah*Bl + Al*Bh  (lo*lo dropped).
// EPI 0: none | 1: relu(+bias) | 2: BatchNorm eval (+bias)
// ---------------------------------------------------------------------------
#define BUF_BYTES 32768

template<int EPI>
__global__ __launch_bounds__(256, 1)
void mma_gemm(const float* __restrict__ A, const float* __restrict__ B,
              float* __restrict__ C, int M, int N, int K,
              const float* __restrict__ bias,
              const float* __restrict__ bng, const float* __restrict__ bnb,
              const float* __restrict__ bnm, const float* __restrict__ bnv)
{
    extern __shared__ __align__(128) char smc[];   // 64 KB: 2 buffers
    const uint32_t sbase = smem_u32(smc);

    const int tid  = threadIdx.x;
    const int lane = tid & 31;
    const int wid  = tid >> 5;
    const int wm   = (wid >> 2) * 64;    // warp M offset within CTA tile
    const int wn   = (wid & 3) * 32;     // warp N offset
    const int rowBase = blockIdx.y * 128;
    const int colBase = blockIdx.x * 128;

    float acc[4][4][4];
#pragma unroll
    for (int i = 0; i < 4; i++)
#pragma unroll
        for (int j = 0; j < 4; j++)
#pragma unroll
            for (int r = 0; r < 4; r++) acc[i][j][r] = 0.f;

    // GMEM staging registers
    float4 stA[4];        // A: 4 slots, (tid + s*256)*4 -> m = idx>>5, k = idx&31
    float4 stB[2][2];     // B: 2 slots, (tid + s*256)*8 -> k = idx>>7, n = idx&127

    auto ldg = [&](int k0) {
#pragma unroll
        for (int s = 0; s < 4; s++) {
            const int idx = (tid + s * 256) * 4;
            const int m = idx >> 5, k = idx & 31;
            stA[s] = *reinterpret_cast<const float4*>(
                A + (size_t)(rowBase + m) * K + k0 + k);
        }
#pragma unroll
        for (int s = 0; s < 2; s++) {
            const int idx = (tid + s * 256) * 8;
            const int k = idx >> 7, n = idx & 127;
            const float* p = B + (size_t)(k0 + k) * N + colBase + n;
            stB[s][0] = *reinterpret_cast<const float4*>(p);
            stB[s][1] = *reinterpret_cast<const float4*>(p + 4);
        }
    };

    auto sts = [&](int buf) {
        char* base = smc + buf * BUF_BYTES;
#pragma unroll
        for (int s = 0; s < 4; s++) {
            const int idx = (tid + s * 256) * 4;
            const int m = idx >> 5, k = idx & 31;
            uint32_t h0, l0, h1, l1;
            split_pack(stA[s].x, stA[s].y, h0, l0);
            split_pack(stA[s].z, stA[s].w, h1, l1);
            const uint32_t off = sw_a((uint32_t)(m * 64 + k * 2));  // 8B aligned
            *reinterpret_cast<uint2*>(base + off)        = make_uint2(h0, h1);
            *reinterpret_cast<uint2*>(base + 8192 + off) = make_uint2(l0, l1);
        }
#pragma unroll
        for (int s = 0; s < 2; s++) {
            const int idx = (tid + s * 256) * 8;
            const int k = idx >> 7, n = idx & 127;
            uint32_t h[4], l[4];
            split_pack(stB[s][0].x, stB[s][0].y, h[0], l[0]);
            split_pack(stB[s][0].z, stB[s][0].w, h[1], l[1]);
            split_pack(stB[s][1].x, stB[s][1].y, h[2], l[2]);
            split_pack(stB[s][1].z, stB[s][1].w, h[3], l[3]);
            const uint32_t off = sw_b((uint32_t)(k * 256 + n * 2));  // 16B aligned
            *reinterpret_cast<uint4*>(base + 16384 + off) = make_uint4(h[0], h[1], h[2], h[3]);
            *reinterpret_cast<uint4*>(base + 24576 + off) = make_uint4(l[0], l[1], l[2], l[3]);
        }
    };

    auto compute = [&](int buf) {
        const uint32_t sA_hi = sbase + buf * BUF_BYTES;
        const uint32_t sA_lo = sA_hi + 8192;
        const uint32_t sB_hi = sA_hi + 16384;
        const uint32_t sB_lo = sA_hi + 24576;
#pragma unroll
        for (int ks = 0; ks < 2; ks++) {
            const int k0 = ks * 16;
            // A fragments: hi/lo, 4 m-frags of 16x16
            uint32_t af[2][4][4];
            {
                const int m_lane = lane & 15;
                const int k_lane = k0 + ((lane >> 4) << 3);
#pragma unroll
                for (int mf = 0; mf < 4; mf++) {
                    const uint32_t off = sw_a(
                        (uint32_t)((wm + mf * 16 + m_lane) * 64 + k_lane * 2));
                    ldsm_x4(af[0][mf], sA_hi + off);
                    ldsm_x4(af[1][mf], sA_lo + off);
                }
            }
            // B fragments: hi/lo, 2 groups x4.trans, each covers 2 n-frags
            uint32_t bfr[2][2][4];
            {
                const int mat = lane >> 3, wi = lane & 7;
                const int k_lane = k0 + (mat & 1) * 8 + wi;
#pragma unroll
                for (int grp = 0; grp < 2; grp++) {
                    const int n_lane = wn + grp * 16 + (mat >> 1) * 8;
                    const uint32_t off = sw_b((uint32_t)(k_lane * 256 + n_lane * 2));
                    ldsm_x4_t(bfr[0][grp], sB_hi + off);
                    ldsm_x4_t(bfr[1][grp], sB_lo + off);
                }
            }
#pragma unroll
            for (int mf = 0; mf < 4; mf++)
#pragma unroll
                for (int nf = 0; nf < 4; nf++) {
                    const int g = nf >> 1, q = (nf & 1) * 2;
                    mma_bf16(acc[mf][nf], af[0][mf], bfr[0][g][q], bfr[0][g][q + 1]); // Ah*Bh
                    mma_bf16(acc[mf][nf], af[0][mf], bfr[1][g][q], bfr[1][g][q + 1]); // Ah*Bl
                    mma_bf16(acc[mf][nf], af[1][mf], bfr[0][g][q], bfr[0][g][q + 1]); // Al*Bh
                }
        }
    };

    const int nk = K >> 5;   // K / 32
    ldg(0);
    sts(0);
    __syncthreads();
    for (int it = 0; it < nk; it++) {
        const int buf = it & 1;
        if (it + 1 < nk) ldg((it + 1) << 5);   // prefetch next chunk to regs
        compute(buf);                           // tensor pipe busy; LDG in flight
        if (it + 1 < nk) sts(buf ^ 1);          // fill other buffer (drained at it-1 sync)
        __syncthreads();                        // single barrier per chunk
    }

    // ---- epilogue ----
    const int g   = lane >> 2;
    const int tig = lane & 3;
#pragma unroll
    for (int mf = 0; mf < 4; mf++) {
#pragma unroll
        for (int nf = 0; nf < 4; nf++) {
            const int row = rowBase + wm + mf * 16 + g;
            const int col = colBase + wn + nf * 8 + tig * 2;
            float v0 = acc[mf][nf][0], v1 = acc[mf][nf][1];
            float v2 = acc[mf][nf][2], v3 = acc[mf][nf][3];
            if constexpr (EPI >= 1) {
                const float b0 = bias[col], b1 = bias[col + 1];
                v0 += b0; v1 += b1; v2 += b0; v3 += b1;
            }
            if constexpr (EPI == 1) {
                v0 = fmaxf(v0, 0.f); v1 = fmaxf(v1, 0.f);
                v2 = fmaxf(v2, 0.f); v3 = fmaxf(v3, 0.f);
            }
            if constexpr (EPI == 2) {
                const float i0 = bng[col]     * rsqrtf(bnv[col]     + BN_EPS);
                const float i1 = bng[col + 1] * rsqrtf(bnv[col + 1] + BN_EPS);
                const float a0 = bnb[col]     - bnm[col]     * i0;
                const float a1 = bnb[col + 1] - bnm[col + 1] * i1;
                v0 = v0 * i0 + a0; v1 = v1 * i1 + a1;
                v2 = v2 * i0 + a0; v3 = v3 * i1 + a1;
            }
            *reinterpret_cast<float2*>(C + (size_t)row * N + col)       = make_float2(v0, v1);
            *reinterpret_cast<float2*>(C + (size_t)(row + 8) * N + col) = make_float2(v2, v3);
        }
    }
}

// ---------------------------------------------------------------------------
extern "C" void kernel_launch(void* const* d_in, const int* in_sizes, int n_in,
                              void* d_out, int out_size)
{
    const float* x     = (const float*)d_in[0];
    const float* IFadj = (const float*)d_in[1];
    const float* adj   = (const float*)d_in[2];
    const float* W1    = (const float*)d_in[3];
    const float* b1    = (const float*)d_in[4];
    const float* W2    = (const float*)d_in[5];
    const float* b2    = (const float*)d_in[6];
    const float* bng   = (const float*)d_in[7];
    const float* bnb   = (const float*)d_in[8];
    const float* bnm   = (const float*)d_in[9];
    const float* bnv   = (const float*)d_in[10];
    float* out = (float*)d_out;

    float *s1, *h, *s2;
    cudaGetSymbolAddress((void**)&s1, g_S1);
    cudaGetSymbolAddress((void**)&h,  g_H);
    cudaGetSymbolAddress((void**)&s2, g_S2);

    const int smem = 2 * BUF_BYTES;   // 64 KB dynamic
    cudaFuncSetAttribute(mma_gemm<0>, cudaFuncAttributeMaxDynamicSharedMemorySize, smem);
    cudaFuncSetAttribute(mma_gemm<1>, cudaFuncAttributeMaxDynamicSharedMemorySize, smem);
    cudaFuncSetAttribute(mma_gemm<2>, cudaFuncAttributeMaxDynamicSharedMemorySize, smem);

    const dim3 blk(256);

    // 1) S1 = x @ W1                      M=8192 N=512 K=1024
    mma_gemm<0><<<dim3(NHID / 128, N_NODES / 128), blk, smem>>>(
        x, W1, s1, N_NODES, NHID, NFEAT, nullptr, nullptr, nullptr, nullptr, nullptr);

    // 2) H = relu(IFadj @ S1 + b1)        M=8192 N=512 K=8192  (dominant)
    mma_gemm<1><<<dim3(NHID / 128, N_NODES / 128), blk, smem>>>(
        IFadj, s1, h, N_NODES, NHID, N_NODES, b1, nullptr, nullptr, nullptr, nullptr);

    // 3) S2 = H @ W2                      M=8192 N=256 K=512
    mma_gemm<0><<<dim3(OUTD / 128, N_NODES / 128), blk, smem>>>(
        h, W2, s2, N_NODES, OUTD, NHID, nullptr, nullptr, nullptr, nullptr, nullptr);

    // 4) out = BN(adj @ S2 + b2)          M=8192 N=256 K=8192
    mma_gemm<2><<<dim3(OUTD / 128, N_NODES / 128), blk, smem>>>(
        adj, s2, out, N_NODES, OUTD, N_NODES, b2, bng, bnb, bnm, bnv);
}